// round 1
// baseline (speedup 1.0000x reference)
#include <cuda_runtime.h>
#include <cuda_bf16.h>
#include <cstdint>

// Problem constants (fixed by setup_inputs: T=128, B=64, D=4096, K_BITS=128)
#define N_ROWS 8192
#define DIMK   4096
#define NBITS  128

// GEMM tiling
#define BM 64          // rows per block
#define KT 64          // k-chunk
#define SK (KT + 4)    // padded smem stride (bf16 elems)

// Scratch (device globals; no allocation allowed)
__device__ uint4    g_keys[N_ROWS];
__device__ unsigned g_hash[N_ROWS];

__device__ __forceinline__ void mma_bf16(float c[4], const unsigned a[4], const unsigned b[2]) {
    asm volatile(
        "mma.sync.aligned.m16n8k16.row.col.f32.bf16.bf16.f32 "
        "{%0,%1,%2,%3}, {%4,%5,%6,%7}, {%8,%9}, {%0,%1,%2,%3};\n"
        : "+f"(c[0]), "+f"(c[1]), "+f"(c[2]), "+f"(c[3])
        : "r"(a[0]), "r"(a[1]), "r"(a[2]), "r"(a[3]), "r"(b[0]), "r"(b[1]));
}

// Stage 1: bf16 tensor-core GEMM [BM x 128] per block, sign-pack to 128-bit keys + 32-bit hash.
__global__ __launch_bounds__(256, 1)
void gemm_sign_kernel(const float* __restrict__ lat, const float* __restrict__ Amat) {
    // smem aliasing: operands (26112 B) and C tile (32768 B) are used in disjoint phases.
    __shared__ __align__(16) char smem_raw[32768 + 1024];
    __nv_bfloat16* lat_s = reinterpret_cast<__nv_bfloat16*>(smem_raw);            // [BM][SK]
    __nv_bfloat16* a_s   = lat_s + BM * SK;                                        // [128][SK]
    float*         Cs    = reinterpret_cast<float*>(smem_raw);                     // [64][128]
    unsigned*      wsm   = reinterpret_cast<unsigned*>(smem_raw + 32768);          // [64][4]

    const int tid  = threadIdx.x;
    const int wid  = tid >> 5;
    const int lane = tid & 31;
    const int wm   = wid & 1;        // warp m index (2)
    const int wn   = wid >> 1;       // warp n index (4)
    const int g    = lane >> 2;      // group id (row within 8)
    const int tig  = lane & 3;       // thread in group

    const int rowBase = blockIdx.x * BM;

    float acc[2][4][4];
#pragma unroll
    for (int mi = 0; mi < 2; mi++)
#pragma unroll
        for (int ni = 0; ni < 4; ni++)
#pragma unroll
            for (int c = 0; c < 4; c++) acc[mi][ni][c] = 0.f;

    for (int kc = 0; kc < DIMK / KT; kc++) {
        const int k0 = kc * KT;
        // ---- load latent tile [BM x KT] fp32 -> bf16 smem ----
#pragma unroll
        for (int q = 0; q < 4; q++) {
            int f  = tid + 256 * q;            // float4 index over BM*KT/4 = 1024
            int r  = f >> 4;                   // 16 float4 per row
            int cf = f & 15;
            float4 v = *reinterpret_cast<const float4*>(
                &lat[(size_t)(rowBase + r) * DIMK + k0 + cf * 4]);
            __nv_bfloat162 p0 = __floats2bfloat162_rn(v.x, v.y);
            __nv_bfloat162 p1 = __floats2bfloat162_rn(v.z, v.w);
            __nv_bfloat162* dst = reinterpret_cast<__nv_bfloat162*>(&lat_s[r * SK + cf * 4]);
            dst[0] = p0; dst[1] = p1;
        }
        // ---- load A tile [128 x KT] fp32 -> bf16 smem ----
#pragma unroll
        for (int q = 0; q < 8; q++) {
            int f  = tid + 256 * q;            // float4 index over 128*KT/4 = 2048
            int r  = f >> 4;
            int cf = f & 15;
            float4 v = *reinterpret_cast<const float4*>(
                &Amat[(size_t)r * DIMK + k0 + cf * 4]);
            __nv_bfloat162 p0 = __floats2bfloat162_rn(v.x, v.y);
            __nv_bfloat162 p1 = __floats2bfloat162_rn(v.z, v.w);
            __nv_bfloat162* dst = reinterpret_cast<__nv_bfloat162*>(&a_s[r * SK + cf * 4]);
            dst[0] = p0; dst[1] = p1;
        }
        __syncthreads();

        // ---- 4 k-steps of m16n8k16 ----
#pragma unroll
        for (int ks = 0; ks < 4; ks++) {
            const int kb = ks * 16;
            unsigned afr[2][4];
#pragma unroll
            for (int mi = 0; mi < 2; mi++) {
                int row = wm * 32 + mi * 16;
                afr[mi][0] = *reinterpret_cast<const unsigned*>(&lat_s[(row + g    ) * SK + kb + 2 * tig    ]);
                afr[mi][1] = *reinterpret_cast<const unsigned*>(&lat_s[(row + g + 8) * SK + kb + 2 * tig    ]);
                afr[mi][2] = *reinterpret_cast<const unsigned*>(&lat_s[(row + g    ) * SK + kb + 2 * tig + 8]);
                afr[mi][3] = *reinterpret_cast<const unsigned*>(&lat_s[(row + g + 8) * SK + kb + 2 * tig + 8]);
            }
            unsigned bfr[4][2];
#pragma unroll
            for (int ni = 0; ni < 4; ni++) {
                int col = wn * 32 + ni * 8;
                bfr[ni][0] = *reinterpret_cast<const unsigned*>(&a_s[(col + g) * SK + kb + 2 * tig    ]);
                bfr[ni][1] = *reinterpret_cast<const unsigned*>(&a_s[(col + g) * SK + kb + 2 * tig + 8]);
            }
#pragma unroll
            for (int mi = 0; mi < 2; mi++)
#pragma unroll
                for (int ni = 0; ni < 4; ni++)
                    mma_bf16(acc[mi][ni], afr[mi], bfr[ni]);
        }
        __syncthreads();
    }

    // ---- store C to smem (aliases operand smem; safe after the final sync) ----
#pragma unroll
    for (int mi = 0; mi < 2; mi++) {
#pragma unroll
        for (int ni = 0; ni < 4; ni++) {
            int row = wm * 32 + mi * 16 + g;
            int col = wn * 32 + ni * 8 + tig * 2;
            Cs[row * 128 + col]           = acc[mi][ni][0];
            Cs[row * 128 + col + 1]       = acc[mi][ni][1];
            Cs[(row + 8) * 128 + col]     = acc[mi][ni][2];
            Cs[(row + 8) * 128 + col + 1] = acc[mi][ni][3];
        }
    }
    __syncthreads();

    // ---- sign-pack: thread tid -> (row tid>>2, word tid&3) ----
    {
        int r = tid >> 2, w = tid & 3;
        unsigned word = 0;
#pragma unroll
        for (int b = 0; b < 32; b++)
            word |= (Cs[r * 128 + w * 32 + b] > 0.0f) ? (1u << b) : 0u;
        wsm[r * 4 + w] = word;
        reinterpret_cast<unsigned*>(g_keys)[(size_t)(rowBase + r) * 4 + w] = word;
    }
    __syncthreads();

    if (tid < 64) {
        unsigned w0 = wsm[tid * 4 + 0], w1 = wsm[tid * 4 + 1];
        unsigned w2 = wsm[tid * 4 + 2], w3 = wsm[tid * 4 + 3];
        unsigned h = w0 * 0x9E3779B1u;
        h ^= w1; h *= 0x85EBCA77u;
        h ^= w2; h *= 0xC2B2AE3Du;
        h ^= w3; h *= 0x27D4EB2Fu;
        h ^= h >> 15;
        g_hash[rowBase + tid] = h;
    }
}

// Stage 2: counts[i] = #{j<=i : key_j == key_i}; out[i] = rsqrt(counts[i]).
// Hash chunks staged in smem; uint4-wide compares; full-key verify only on hash hit.
#define CHUNK 2048
__global__ __launch_bounds__(256, 4)
void count_kernel(float* __restrict__ out) {
    __shared__ __align__(16) unsigned sh[CHUNK];
    const int tid = threadIdx.x;
    const int i   = blockIdx.x * 256 + tid;

    const unsigned hi = g_hash[i];
    const uint4    ki = g_keys[i];
    int cnt = 0;

    const int blockMaxI = blockIdx.x * 256 + 255;
    const int nChunks   = blockMaxI / CHUNK + 1;

    for (int c = 0; c < nChunks; c++) {
        const int base = c * CHUNK;
        // cooperative load of CHUNK hashes (always in-bounds: N % CHUNK == 0)
#pragma unroll
        for (int q = 0; q < CHUNK / 256; q++)
            sh[tid + 256 * q] = g_hash[base + tid + 256 * q];
        __syncthreads();

        int lim = i + 1 - base;
        if (lim > 0) {
            if (lim > CHUNK) lim = CHUNK;
            const int l4 = lim & ~3;
            const uint4* sh4 = reinterpret_cast<const uint4*>(sh);
            for (int j = 0; j < l4; j += 4) {
                uint4 hv = sh4[j >> 2];
                if (hv.x == hi) { uint4 kj = g_keys[base + j    ]; cnt += (kj.x==ki.x && kj.y==ki.y && kj.z==ki.z && kj.w==ki.w); }
                if (hv.y == hi) { uint4 kj = g_keys[base + j + 1]; cnt += (kj.x==ki.x && kj.y==ki.y && kj.z==ki.z && kj.w==ki.w); }
                if (hv.z == hi) { uint4 kj = g_keys[base + j + 2]; cnt += (kj.x==ki.x && kj.y==ki.y && kj.z==ki.z && kj.w==ki.w); }
                if (hv.w == hi) { uint4 kj = g_keys[base + j + 3]; cnt += (kj.x==ki.x && kj.y==ki.y && kj.z==ki.z && kj.w==ki.w); }
            }
            for (int j = l4; j < lim; j++) {
                if (sh[j] == hi) {
                    uint4 kj = g_keys[base + j];
                    cnt += (kj.x==ki.x && kj.y==ki.y && kj.z==ki.z && kj.w==ki.w);
                }
            }
        }
        __syncthreads();
    }

    out[i] = rsqrtf((float)cnt);
}

extern "C" void kernel_launch(void* const* d_in, const int* in_sizes, int n_in,
                              void* d_out, int out_size) {
    const float* lat  = (const float*)d_in[0];   // [T,B,D] = [128,64,4096]
    const float* Amat = (const float*)d_in[1];   // [128, 4096]
    float* out = (float*)d_out;                  // [T,B] fp32

    gemm_sign_kernel<<<N_ROWS / BM, 256>>>(lat, Amat);
    count_kernel<<<N_ROWS / 256, 256>>>(out);
}

// round 2
// speedup vs baseline: 2.7897x; 2.7897x over previous
#include <cuda_runtime.h>
#include <cuda_bf16.h>
#include <cstdint>

// Problem constants (fixed by setup_inputs: T=128, B=64, D=4096, K_BITS=128)
#define N_ROWS 8192
#define DIMK   4096

// GEMM tiling
#define BM 64          // rows per block
#define KT 64          // k-chunk
#define SK (KT + 4)    // padded smem stride (bf16 elems)
#define BUFSZ ((BM + 128) * SK)   // bf16 elems per double-buffer stage

// Scratch (device globals; no allocation allowed)
__device__ uint4    g_keys[N_ROWS];
__device__ unsigned g_hash[N_ROWS];
__device__ int      g_cnt[N_ROWS];

__device__ __forceinline__ void mma_bf16(float c[4], const unsigned a[4], const unsigned b[2]) {
    asm volatile(
        "mma.sync.aligned.m16n8k16.row.col.f32.bf16.bf16.f32 "
        "{%0,%1,%2,%3}, {%4,%5,%6,%7}, {%8,%9}, {%0,%1,%2,%3};\n"
        : "+f"(c[0]), "+f"(c[1]), "+f"(c[2]), "+f"(c[3])
        : "r"(a[0]), "r"(a[1]), "r"(a[2]), "r"(a[3]), "r"(b[0]), "r"(b[1]));
}

// Stage 1: bf16 tensor-core GEMM [BM x 128] per block, sign-pack to 128-bit keys + hash.
// Register-prefetch + double-buffered smem: global loads for chunk kc+1 overlap MMAs on kc.
__global__ __launch_bounds__(256, 1)
void gemm_sign_kernel(const float* __restrict__ lat, const float* __restrict__ Amat) {
    // smem: two operand buffers (2 * 26112 bf16 = 104448 B? no: elems) + aliased C tile.
    // BUFSZ = 192*68 = 13056 bf16 elems = 26112 B per stage; 2 stages = 52224 B.
    __shared__ __align__(16) char smem_raw[2 * BUFSZ * 2 + 1024];
    __nv_bfloat16* buf  = reinterpret_cast<__nv_bfloat16*>(smem_raw);
    float*         Cs   = reinterpret_cast<float*>(smem_raw);                 // [64][128] = 32768 B (aliases bufs, used after final sync)
    unsigned*      wsm  = reinterpret_cast<unsigned*>(smem_raw + 2 * BUFSZ * 2); // [64][4]

    const int tid  = threadIdx.x;
    const int wid  = tid >> 5;
    const int lane = tid & 31;
    const int wm   = wid & 1;        // warp m index (2)
    const int wn   = wid >> 1;       // warp n index (4)
    const int g    = lane >> 2;      // group id (row within 8)
    const int tig  = lane & 3;       // thread in group

    const int rowBase = blockIdx.x * BM;

    // zero visit counters for this block's rows (graph-replay safe: done every launch)
    if (tid < BM) g_cnt[rowBase + tid] = 0;

    float acc[2][4][4];
#pragma unroll
    for (int mi = 0; mi < 2; mi++)
#pragma unroll
        for (int ni = 0; ni < 4; ni++)
#pragma unroll
            for (int c = 0; c < 4; c++) acc[mi][ni][c] = 0.f;

    // per-thread load coordinates (constant across chunks)
    // latent: 4 float4s; A: 8 float4s
    int lr[4], lc[4], ar[8], ac[8];
#pragma unroll
    for (int q = 0; q < 4; q++) {
        int f = tid + 256 * q;       // over BM*KT/4 = 1024 float4s, 16 per row
        lr[q] = f >> 4; lc[q] = (f & 15) * 4;
    }
#pragma unroll
    for (int q = 0; q < 8; q++) {
        int f = tid + 256 * q;       // over 128*KT/4 = 2048 float4s
        ar[q] = f >> 4; ac[q] = (f & 15) * 4;
    }

    float4 rl[4], ra[8];
    // prefetch chunk 0
#pragma unroll
    for (int q = 0; q < 4; q++)
        rl[q] = *reinterpret_cast<const float4*>(&lat[(size_t)(rowBase + lr[q]) * DIMK + lc[q]]);
#pragma unroll
    for (int q = 0; q < 8; q++)
        ra[q] = *reinterpret_cast<const float4*>(&Amat[(size_t)ar[q] * DIMK + ac[q]]);

    int p = 0;
    for (int kc = 0; kc < DIMK / KT; kc++) {
        __nv_bfloat16* lat_s = buf + p * BUFSZ;
        __nv_bfloat16* a_s   = lat_s + BM * SK;

        // convert + store current chunk to smem
#pragma unroll
        for (int q = 0; q < 4; q++) {
            __nv_bfloat162* dst = reinterpret_cast<__nv_bfloat162*>(&lat_s[lr[q] * SK + lc[q]]);
            dst[0] = __floats2bfloat162_rn(rl[q].x, rl[q].y);
            dst[1] = __floats2bfloat162_rn(rl[q].z, rl[q].w);
        }
#pragma unroll
        for (int q = 0; q < 8; q++) {
            __nv_bfloat162* dst = reinterpret_cast<__nv_bfloat162*>(&a_s[ar[q] * SK + ac[q]]);
            dst[0] = __floats2bfloat162_rn(ra[q].x, ra[q].y);
            dst[1] = __floats2bfloat162_rn(ra[q].z, ra[q].w);
        }
        __syncthreads();

        // prefetch next chunk (overlaps with MMAs below)
        if (kc + 1 < DIMK / KT) {
            const int k0 = (kc + 1) * KT;
#pragma unroll
            for (int q = 0; q < 4; q++)
                rl[q] = *reinterpret_cast<const float4*>(&lat[(size_t)(rowBase + lr[q]) * DIMK + k0 + lc[q]]);
#pragma unroll
            for (int q = 0; q < 8; q++)
                ra[q] = *reinterpret_cast<const float4*>(&Amat[(size_t)ar[q] * DIMK + k0 + ac[q]]);
        }

        // 4 k-steps of m16n8k16
#pragma unroll
        for (int ks = 0; ks < 4; ks++) {
            const int kb = ks * 16;
            unsigned afr[2][4];
#pragma unroll
            for (int mi = 0; mi < 2; mi++) {
                int row = wm * 32 + mi * 16;
                afr[mi][0] = *reinterpret_cast<const unsigned*>(&lat_s[(row + g    ) * SK + kb + 2 * tig    ]);
                afr[mi][1] = *reinterpret_cast<const unsigned*>(&lat_s[(row + g + 8) * SK + kb + 2 * tig    ]);
                afr[mi][2] = *reinterpret_cast<const unsigned*>(&lat_s[(row + g    ) * SK + kb + 2 * tig + 8]);
                afr[mi][3] = *reinterpret_cast<const unsigned*>(&lat_s[(row + g + 8) * SK + kb + 2 * tig + 8]);
            }
            unsigned bfr[4][2];
#pragma unroll
            for (int ni = 0; ni < 4; ni++) {
                int col = wn * 32 + ni * 8;
                bfr[ni][0] = *reinterpret_cast<const unsigned*>(&a_s[(col + g) * SK + kb + 2 * tig    ]);
                bfr[ni][1] = *reinterpret_cast<const unsigned*>(&a_s[(col + g) * SK + kb + 2 * tig + 8]);
            }
#pragma unroll
            for (int mi = 0; mi < 2; mi++)
#pragma unroll
                for (int ni = 0; ni < 4; ni++)
                    mma_bf16(acc[mi][ni], afr[mi], bfr[ni]);
        }
        p ^= 1;
        // no trailing sync needed: next store targets the other buffer, and the
        // write in iter kc+2 to this buffer is ordered after the sync in kc+1.
    }
    __syncthreads();   // all MMA smem reads done before aliasing Cs over the buffers

    // ---- store C to smem ----
#pragma unroll
    for (int mi = 0; mi < 2; mi++) {
#pragma unroll
        for (int ni = 0; ni < 4; ni++) {
            int row = wm * 32 + mi * 16 + g;
            int col = wn * 32 + ni * 8 + tig * 2;
            Cs[row * 128 + col]           = acc[mi][ni][0];
            Cs[row * 128 + col + 1]       = acc[mi][ni][1];
            Cs[(row + 8) * 128 + col]     = acc[mi][ni][2];
            Cs[(row + 8) * 128 + col + 1] = acc[mi][ni][3];
        }
    }
    __syncthreads();

    // ---- sign-pack: thread tid -> (row tid>>2, word tid&3) ----
    {
        int r = tid >> 2, w = tid & 3;
        unsigned word = 0;
#pragma unroll
        for (int b = 0; b < 32; b++)
            word |= (Cs[r * 128 + w * 32 + b] > 0.0f) ? (1u << b) : 0u;
        wsm[r * 4 + w] = word;
        reinterpret_cast<unsigned*>(g_keys)[(size_t)(rowBase + r) * 4 + w] = word;
    }
    __syncthreads();

    if (tid < BM) {
        unsigned w0 = wsm[tid * 4 + 0], w1 = wsm[tid * 4 + 1];
        unsigned w2 = wsm[tid * 4 + 2], w3 = wsm[tid * 4 + 3];
        unsigned h = w0 * 0x9E3779B1u;
        h ^= w1; h *= 0x85EBCA77u;
        h ^= w2; h *= 0xC2B2AE3Du;
        h ^= w3; h *= 0x27D4EB2Fu;
        h ^= h >> 15;
        g_hash[rowBase + tid] = h;
    }
}

// Stage 2: tile-parallel prefix-duplicate count.
// Grid (32, 32): block (tj, ti) handles i in [ti*256, ti*256+256), j in [tj*256, ...).
// Upper-triangle blocks (tj > ti) exit immediately. Partial counts -> atomicAdd.
#define TI 256
__global__ __launch_bounds__(TI, 8)
void count_tile_kernel() {
    const int ti = blockIdx.y, tj = blockIdx.x;
    if (tj > ti) return;

    __shared__ __align__(16) unsigned shh[TI];
    const int tid   = threadIdx.x;
    const int i     = ti * TI + tid;
    const int jbase = tj * TI;

    shh[tid] = g_hash[jbase + tid];
    const unsigned hi = g_hash[i];
    const uint4    ki = g_keys[i];
    __syncthreads();

    const int lim = (ti == tj) ? (tid + 1) : TI;
    const int l4  = lim & ~3;
    int cnt = 0;

    const uint4* sh4 = reinterpret_cast<const uint4*>(shh);
    for (int j = 0; j < l4; j += 4) {
        uint4 hv = sh4[j >> 2];
        if (hv.x == hi) { uint4 kj = g_keys[jbase + j    ]; cnt += (kj.x==ki.x && kj.y==ki.y && kj.z==ki.z && kj.w==ki.w); }
        if (hv.y == hi) { uint4 kj = g_keys[jbase + j + 1]; cnt += (kj.x==ki.x && kj.y==ki.y && kj.z==ki.z && kj.w==ki.w); }
        if (hv.z == hi) { uint4 kj = g_keys[jbase + j + 2]; cnt += (kj.x==ki.x && kj.y==ki.y && kj.z==ki.z && kj.w==ki.w); }
        if (hv.w == hi) { uint4 kj = g_keys[jbase + j + 3]; cnt += (kj.x==ki.x && kj.y==ki.y && kj.z==ki.z && kj.w==ki.w); }
    }
    for (int j = l4; j < lim; j++) {
        if (shh[j] == hi) {
            uint4 kj = g_keys[jbase + j];
            cnt += (kj.x==ki.x && kj.y==ki.y && kj.z==ki.z && kj.w==ki.w);
        }
    }

    if (cnt) atomicAdd(&g_cnt[i], cnt);
}

// Stage 3: finalize — intrinsic reward.
__global__ void finalize_kernel(float* __restrict__ out) {
    int i = blockIdx.x * 256 + threadIdx.x;
    out[i] = rsqrtf((float)g_cnt[i]);
}

extern "C" void kernel_launch(void* const* d_in, const int* in_sizes, int n_in,
                              void* d_out, int out_size) {
    const float* lat  = (const float*)d_in[0];   // [T,B,D] = [128,64,4096]
    const float* Amat = (const float*)d_in[1];   // [128, 4096]
    float* out = (float*)d_out;                  // [T,B] fp32

    gemm_sign_kernel<<<N_ROWS / BM, 256>>>(lat, Amat);
    dim3 cgrid(N_ROWS / TI, N_ROWS / TI);
    count_tile_kernel<<<cgrid, TI>>>();
    finalize_kernel<<<N_ROWS / 256, 256>>>(out);
}

// round 3
// speedup vs baseline: 3.4504x; 1.2369x over previous
#include <cuda_runtime.h>
#include <cuda_bf16.h>
#include <cstdint>

// Problem constants (fixed: T=128, B=64, D=4096, K_BITS=128)
#define N_ROWS 8192
#define DIMK   4096

// GEMM tiling: per block M=32 rows of latent, N=128 (all bits), K-chunk 64.
#define BM 32
#define KT 64
#define SK 72             // bf16 elems per smem row (144 B; conflict-free LDSM)
#define SKB 144
#define L_STAGE (BM * SKB)            // 4608 B
#define A_STAGE (128 * SKB)           // 18432 B
#define A_BASE  (2 * L_STAGE)         // 9216
#define WSM_OFF (A_BASE + 2 * A_STAGE) // 46080
#define SMEM_BYTES (WSM_OFF + 512)     // 46592 < 48K static limit
#define CS_STRIDE 132                  // padded fp32 C stride

// Scratch (device globals; no allocation allowed)
__device__ uint4         g_keys[N_ROWS];
__device__ unsigned      g_hash[N_ROWS];
__device__ int           g_cnt[N_ROWS];
__device__ __nv_bfloat16 g_Abf[128 * DIMK];

#define CP_ASYNC16(sa, ga) asm volatile("cp.async.cg.shared.global [%0], [%1], 16;\n" :: "r"(sa), "l"(ga))
#define CP_COMMIT()        asm volatile("cp.async.commit_group;\n" ::)
#define CP_WAIT0()         asm volatile("cp.async.wait_group 0;\n" ::)

__device__ __forceinline__ void ldsm4(unsigned &r0, unsigned &r1, unsigned &r2, unsigned &r3, unsigned addr) {
    asm volatile("ldmatrix.sync.aligned.m8n8.x4.shared.b16 {%0,%1,%2,%3}, [%4];\n"
                 : "=r"(r0), "=r"(r1), "=r"(r2), "=r"(r3) : "r"(addr));
}

__device__ __forceinline__ void mma_bf16(float c[4], const unsigned a[4], unsigned b0, unsigned b1) {
    asm volatile(
        "mma.sync.aligned.m16n8k16.row.col.f32.bf16.bf16.f32 "
        "{%0,%1,%2,%3}, {%4,%5,%6,%7}, {%8,%9}, {%0,%1,%2,%3};\n"
        : "+f"(c[0]), "+f"(c[1]), "+f"(c[2]), "+f"(c[3])
        : "r"(a[0]), "r"(a[1]), "r"(a[2]), "r"(a[3]), "r"(b0), "r"(b1));
}

// Stage 0: pre-convert the fixed projection matrix A to bf16 (2MB -> 1MB, once per launch).
__global__ void convertA_kernel(const float* __restrict__ A) {
    int i = blockIdx.x * 256 + threadIdx.x;   // over 128*4096/4 = 131072 float4
    float4 v = reinterpret_cast<const float4*>(A)[i];
    __nv_bfloat162 h0 = __floats2bfloat162_rn(v.x, v.y);
    __nv_bfloat162 h1 = __floats2bfloat162_rn(v.z, v.w);
    uint2 p;
    p.x = reinterpret_cast<unsigned&>(h0);
    p.y = reinterpret_cast<unsigned&>(h1);
    reinterpret_cast<uint2*>(g_Abf)[i] = p;
}

// Stage 1: bf16 tensor-core GEMM [32 x 128] per block -> sign-pack 128-bit keys + hash.
// A via 2-stage cp.async ring (bf16, L2-resident); latent via register prefetch + cvt.
// All MMA fragments via ldmatrix.x4 (conflict-free with SKB=144).
__global__ __launch_bounds__(256, 3)
void gemm_sign_kernel(const float* __restrict__ lat) {
    __shared__ __align__(16) char smem[SMEM_BYTES];
    const unsigned sbase = (unsigned)__cvta_generic_to_shared(smem);

    const int tid  = threadIdx.x;
    const int lane = tid & 31;
    const int wid  = tid >> 5;
    const int wm   = wid & 1;     // m tile (2 x 16 rows)
    const int wn   = wid >> 1;    // n tile (4 x 32 cols)
    const int rowBase = blockIdx.x * BM;

    // zero visit counters for this block's rows (graph-replay safe)
    if (tid < BM) g_cnt[rowBase + tid] = 0;

    float acc[4][4];
#pragma unroll
    for (int n = 0; n < 4; n++)
#pragma unroll
        for (int c = 0; c < 4; c++) acc[n][c] = 0.f;

    // --- per-thread cp.async coordinates for A (128 rows x 64 cols bf16 = 16KB/chunk) ---
    unsigned aso[4];
    const __nv_bfloat16* agb[4];
#pragma unroll
    for (int q = 0; q < 4; q++) {
        int f = tid + 256 * q;         // 1024 x 16B chunks, 8 per row
        int row = f >> 3, ch = f & 7;
        aso[q] = sbase + A_BASE + row * SKB + ch * 16;
        agb[q] = g_Abf + (size_t)row * DIMK + ch * 8;
    }
#define ISSUE_A(stage, k0) do { \
        _Pragma("unroll") for (int q = 0; q < 4; q++) \
            CP_ASYNC16(aso[q] + (stage) * A_STAGE, agb[q] + (k0)); \
        CP_COMMIT(); } while (0)

    // --- per-thread latent load coords (32 rows x 64 cols fp32 = 512 float4) ---
    size_t   lgo[2];
    unsigned lso[2];
#pragma unroll
    for (int q = 0; q < 2; q++) {
        int f = tid + 256 * q;         // 16 float4 per row
        int r = f >> 4, c = f & 15;
        lgo[q] = (size_t)(rowBase + r) * DIMK + c * 4;
        lso[q] = r * SKB + c * 8;      // byte offset within L stage
    }

    // --- prologue: A chunk 0 in flight; latent chunk 0 in regs ---
    ISSUE_A(0, 0);
    float4 rl[2];
    rl[0] = *reinterpret_cast<const float4*>(&lat[lgo[0]]);
    rl[1] = *reinterpret_cast<const float4*>(&lat[lgo[1]]);

    // ldmatrix base addresses (lane-dependent; stage offset added per iter)
    const unsigned lmb = sbase + (wm * 16 + (lane & 15)) * SKB + (lane >> 4) * 16;
    const unsigned amb = sbase + A_BASE
                       + (wn * 32 + (lane & 7) + ((lane >> 4) << 3)) * SKB
                       + ((lane >> 3) & 1) * 16;

    const int NC = DIMK / KT;  // 64
    for (int kc = 0; kc < NC; kc++) {
        // convert + store latent chunk kc
        char* Ls = smem + (kc & 1) * L_STAGE;
#pragma unroll
        for (int q = 0; q < 2; q++) {
            __nv_bfloat162 h0 = __floats2bfloat162_rn(rl[q].x, rl[q].y);
            __nv_bfloat162 h1 = __floats2bfloat162_rn(rl[q].z, rl[q].w);
            uint2 pv;
            pv.x = reinterpret_cast<unsigned&>(h0);
            pv.y = reinterpret_cast<unsigned&>(h1);
            *reinterpret_cast<uint2*>(Ls + lso[q]) = pv;
        }
        CP_WAIT0();          // A chunk kc resident
        __syncthreads();

        if (kc + 1 < NC) {
            // safe: stage (kc+1)&1 last read by MMA(kc-1), ordered by the sync above
            ISSUE_A((kc + 1) & 1, (kc + 1) * KT);
            const size_t k0 = (size_t)(kc + 1) * KT;
            rl[0] = *reinterpret_cast<const float4*>(&lat[lgo[0] + k0]);
            rl[1] = *reinterpret_cast<const float4*>(&lat[lgo[1] + k0]);
        }

        const unsigned lb = lmb + (kc & 1) * L_STAGE;
        const unsigned ab = amb + (kc & 1) * A_STAGE;
#pragma unroll
        for (int ks = 0; ks < 4; ks++) {
            unsigned a[4], b0[4], b1[4];
            ldsm4(a[0], a[1], a[2], a[3], lb + ks * 32);
            ldsm4(b0[0], b0[1], b0[2], b0[3], ab + ks * 32);
            ldsm4(b1[0], b1[1], b1[2], b1[3], ab + 16 * SKB + ks * 32);
            mma_bf16(acc[0], a, b0[0], b0[1]);
            mma_bf16(acc[1], a, b0[2], b0[3]);
            mma_bf16(acc[2], a, b1[0], b1[1]);
            mma_bf16(acc[3], a, b1[2], b1[3]);
        }
        // no tail sync: next STS targets the other L stage; ISSUE_A ordered by next sync
    }
    __syncthreads();   // all MMA smem reads done before aliasing C over the buffers

    // --- epilogue: C -> smem (padded), ballot sign-pack, key + hash ---
    float*    Cs  = reinterpret_cast<float*>(smem);
    unsigned* wsm = reinterpret_cast<unsigned*>(smem + WSM_OFF);
    const int g = lane >> 2, tig = lane & 3;
#pragma unroll
    for (int ni = 0; ni < 4; ni++) {
        int row = wm * 16 + g;
        int col = wn * 32 + ni * 8 + 2 * tig;
        *reinterpret_cast<float2*>(&Cs[row * CS_STRIDE + col])       = make_float2(acc[ni][0], acc[ni][1]);
        *reinterpret_cast<float2*>(&Cs[(row + 8) * CS_STRIDE + col]) = make_float2(acc[ni][2], acc[ni][3]);
    }
    __syncthreads();

    // 128 words (32 rows x 4), 8 warps x 16 words; ballot packs 32 signs per instruction
#pragma unroll
    for (int t = 0; t < 16; t++) {
        int idx = wid * 16 + t;
        int row = idx >> 2, w = idx & 3;
        unsigned bits = __ballot_sync(0xffffffffu, Cs[row * CS_STRIDE + w * 32 + lane] > 0.0f);
        if (lane == 0) {
            wsm[idx] = bits;
            reinterpret_cast<unsigned*>(g_keys)[(size_t)(rowBase + row) * 4 + w] = bits;
        }
    }
    __syncthreads();

    if (tid < BM) {
        unsigned w0 = wsm[tid * 4 + 0], w1 = wsm[tid * 4 + 1];
        unsigned w2 = wsm[tid * 4 + 2], w3 = wsm[tid * 4 + 3];
        unsigned h = w0 * 0x9E3779B1u;
        h ^= w1; h *= 0x85EBCA77u;
        h ^= w2; h *= 0xC2B2AE3Du;
        h ^= w3; h *= 0x27D4EB2Fu;
        h ^= h >> 15;
        g_hash[rowBase + tid] = h;
    }
}

// Stage 2: tile-parallel prefix-duplicate count (lower-triangle 256x256 tiles).
#define TI 256
__global__ __launch_bounds__(TI, 8)
void count_tile_kernel() {
    const int ti = blockIdx.y, tj = blockIdx.x;
    if (tj > ti) return;

    __shared__ __align__(16) unsigned shh[TI];
    const int tid   = threadIdx.x;
    const int i     = ti * TI + tid;
    const int jbase = tj * TI;

    shh[tid] = g_hash[jbase + tid];
    const unsigned hi = g_hash[i];
    const uint4    ki = g_keys[i];
    __syncthreads();

    const int lim = (ti == tj) ? (tid + 1) : TI;
    const int l4  = lim & ~3;
    int cnt = 0;

    const uint4* sh4 = reinterpret_cast<const uint4*>(shh);
    for (int j = 0; j < l4; j += 4) {
        uint4 hv = sh4[j >> 2];
        if (hv.x == hi) { uint4 kj = g_keys[jbase + j    ]; cnt += (kj.x==ki.x && kj.y==ki.y && kj.z==ki.z && kj.w==ki.w); }
        if (hv.y == hi) { uint4 kj = g_keys[jbase + j + 1]; cnt += (kj.x==ki.x && kj.y==ki.y && kj.z==ki.z && kj.w==ki.w); }
        if (hv.z == hi) { uint4 kj = g_keys[jbase + j + 2]; cnt += (kj.x==ki.x && kj.y==ki.y && kj.z==ki.z && kj.w==ki.w); }
        if (hv.w == hi) { uint4 kj = g_keys[jbase + j + 3]; cnt += (kj.x==ki.x && kj.y==ki.y && kj.z==ki.z && kj.w==ki.w); }
    }
    for (int j = l4; j < lim; j++) {
        if (shh[j] == hi) {
            uint4 kj = g_keys[jbase + j];
            cnt += (kj.x==ki.x && kj.y==ki.y && kj.z==ki.z && kj.w==ki.w);
        }
    }

    if (cnt) atomicAdd(&g_cnt[i], cnt);
}

// Stage 3: finalize — intrinsic reward.
__global__ void finalize_kernel(float* __restrict__ out) {
    int i = blockIdx.x * 256 + threadIdx.x;
    out[i] = rsqrtf((float)g_cnt[i]);
}

extern "C" void kernel_launch(void* const* d_in, const int* in_sizes, int n_in,
                              void* d_out, int out_size) {
    const float* lat  = (const float*)d_in[0];   // [128,64,4096]
    const float* Amat = (const float*)d_in[1];   // [128,4096]
    float* out = (float*)d_out;                  // [T,B] fp32

    convertA_kernel<<<(128 * DIMK / 4) / 256, 256>>>(Amat);
    gemm_sign_kernel<<<N_ROWS / BM, 256>>>(lat);
    dim3 cgrid(N_ROWS / TI, N_ROWS / TI);
    count_tile_kernel<<<cgrid, TI>>>();
    finalize_kernel<<<N_ROWS / 256, 256>>>(out);
}